// round 7
// baseline (speedup 1.0000x reference)
#include <cuda_runtime.h>
#include <cuda_fp16.h>
#include <cstdint>

// ============================================================================
// KANConv2d fused: out[16384,128] = A[16384,5184] @ Wc[5184,128]
// Single main kernel: per-CTA (M=128 rows) computes activations into SMEM
// (K-chunks of 16 patch-features = 144 halves = 9 k16 steps) and consumes
// them with mma.sync m16n8k16 (fp32 accum). W pre-combined to fp16 in a
// [chunk][oc][144] tiled layout by a small prep kernel, cp.async double-buffered.
// ============================================================================

#define OC      128
#define D_TOT   576
#define NBAS    8
#define NK      5184
#define NCH     36            // K chunks
#define DPC     16            // patch-features per chunk
#define KHC     144           // halves per chunk (= DPC*9)
#define PITCH   304           // bytes per SMEM tile row (144*2=288 + 16 pad)
#define NROWS   16384
#define HW      64

#define TILEB   (128 * PITCH)     // 38912 B per tile buffer

__device__ __align__(16) __half g_Wb[(size_t)NCH * OC * KHC];  // 1.33 MB

// ---------------------------------------------------------------------------
__device__ __forceinline__ uint32_t smem_u32(const void* p) {
    uint32_t a;
    asm("{ .reg .u64 t; cvta.to.shared.u64 t, %1; cvt.u32.u64 %0, t; }"
        : "=r"(a) : "l"(p));
    return a;
}
#define CP_ASYNC16(sa, gp) \
    asm volatile("cp.async.cg.shared.global [%0], [%1], 16;" \
        :: "r"((uint32_t)(sa)), "l"(gp) : "memory")
#define CP_COMMIT() asm volatile("cp.async.commit_group;" ::: "memory")
#define CP_WAIT0()  asm volatile("cp.async.wait_group 0;" ::: "memory")
#define CP_WAIT1()  asm volatile("cp.async.wait_group 1;" ::: "memory")

__device__ __forceinline__ void mma16816(float c[4], const uint32_t a[4],
                                         uint32_t b0, uint32_t b1) {
    asm volatile(
        "mma.sync.aligned.m16n8k16.row.col.f32.f16.f16.f32 "
        "{%0,%1,%2,%3}, {%4,%5,%6,%7}, {%8,%9}, {%0,%1,%2,%3};"
        : "+f"(c[0]), "+f"(c[1]), "+f"(c[2]), "+f"(c[3])
        : "r"(a[0]), "r"(a[1]), "r"(a[2]), "r"(a[3]), "r"(b0), "r"(b1));
}

// ---------------------------------------------------------------------------
// Closed-form activations: silu + 8 uniform cubic B-spline bases.
// Grid knots t_j = (j-3)*0.4 - 1, j=0..11. For v in interval i (t_i<=v<t_{i+1}),
// basis b_k nonzero iff delta=i-k in [0,3]; piece polys in u=(v-t_i)/h.
// ---------------------------------------------------------------------------
__device__ __forceinline__ void acts9(float v, float o[9]) {
    o[0] = v * (1.0f / (1.0f + __expf(-v)));           // silu
    float tpos = (v + 2.2f) * 2.5f;
    float fi = floorf(tpos);
    int i = (int)fi;
    float u = tpos - fi;
    bool valid = (i >= 0) && (i <= 10);
    float u2 = u * u, u3 = u2 * u;
    float P0 = u3 * (1.0f / 6.0f);                      // delta 0: u^3/6
    float P1 = (((-3.0f * u + 3.0f) * u + 3.0f) * u + 1.0f) * (1.0f / 6.0f);
    float P2 = ((3.0f * u - 6.0f) * u2 + 4.0f) * (1.0f / 6.0f);
    float om = 1.0f - u;
    float P3 = om * om * om * (1.0f / 6.0f);            // delta 3: (1-u)^3/6
#pragma unroll
    for (int k = 0; k < 8; ++k) {
        int dlt = i - k;
        float bv = (dlt == 0) ? P0 : (dlt == 1) ? P1 : (dlt == 2) ? P2
                 : (dlt == 3) ? P3 : 0.0f;
        o[1 + k] = valid ? bv : 0.0f;
    }
}

// ---------------------------------------------------------------------------
// Prep kernel: combined weights -> g_Wb[chunk][oc][144] fp16 (coalesced writes)
// ---------------------------------------------------------------------------
__global__ void kan_wcomb_kernel(const float* __restrict__ bw,
                                 const float* __restrict__ sw,
                                 const float* __restrict__ ss) {
    int idx = blockIdx.x * blockDim.x + threadIdx.x;
    if (idx >= NCH * OC * KHC) return;
    int chunk = idx / (OC * KHC);
    int r2    = idx - chunk * (OC * KHC);
    int oc    = r2 / KHC;
    int kl    = r2 - oc * KHC;
    int d     = chunk * DPC + kl / 9;
    int kc    = kl - (kl / 9) * 9;
    float v;
    if (kc == 0) v = bw[oc * D_TOT + d];
    else         v = sw[(oc * D_TOT + d) * NBAS + (kc - 1)] * ss[oc * D_TOT + d];
    g_Wb[idx] = __float2half_rn(v);
}

// ---------------------------------------------------------------------------
// Fused main kernel. grid = 128 M-tiles; 256 threads = 8 warps (2 M x 4 N).
// SMEM: sW double buffer (2x38912) + sA single buffer (38912).
// ---------------------------------------------------------------------------
#define GT 256

__global__ __launch_bounds__(GT, 1)
void kan_fused_kernel(const float* __restrict__ x, float* __restrict__ out) {
    extern __shared__ char dynsmem[];
    const int tid  = threadIdx.x;
    const int lane = tid & 31;
    const int wid  = tid >> 5;
    const int wm   = wid & 1;
    const int wn   = wid >> 1;
    const int mtile = blockIdx.x;

    uint32_t raw = smem_u32(dynsmem);
    uint32_t base = (raw + 1023) & ~1023u;
    char* smem = dynsmem + (base - raw);
    char* sW[2] = { smem, smem + TILEB };
    char* sA    = smem + 2 * TILEB;

    const int bi     = mtile >> 5;                // image index
    const int s_base = (mtile * 128) & 4095;      // spatial base (mult of 128)
    const int ho_b   = s_base >> 6;
    const float* xb  = x + ((size_t)bi * 64 << 12);

    // W cp.async mapping: thread covers half a row (9 x 16B granules)
    const int w_oc   = tid >> 1;
    const int w_half = tid & 1;
    const uint32_t w_sm_off = (uint32_t)w_oc * PITCH + w_half * 144;
    const __half* w_gl = g_Wb + (size_t)w_oc * KHC + w_half * 72;

    // act mapping: dp = d-pair (0..7), rows tid>>3 + 32*it
    const int dp = tid & 7;
    const int rr = tid >> 3;

    float acc[4][4][4];
#pragma unroll
    for (int i = 0; i < 4; ++i)
#pragma unroll
        for (int j = 0; j < 4; ++j)
#pragma unroll
            for (int k = 0; k < 4; ++k) acc[i][j][k] = 0.0f;

    // prefetch W chunk 0
    {
        uint32_t d0 = smem_u32(sW[0]) + w_sm_off;
#pragma unroll
        for (int j = 0; j < 9; ++j)
            CP_ASYNC16(d0 + j * 16, w_gl + j * 8);
        CP_COMMIT();
    }

    for (int i = 0; i < NCH; ++i) {
        __syncthreads();   // prev MMA done reading sA and sW[(i+1)&1]
        if (i + 1 < NCH) {
            uint32_t dsm = smem_u32(sW[(i + 1) & 1]) + w_sm_off;
            const __half* gsrc = w_gl + (size_t)(i + 1) * OC * KHC;
#pragma unroll
            for (int j = 0; j < 9; ++j)
                CP_ASYNC16(dsm + j * 16, gsrc + j * 8);
            CP_COMMIT();
            CP_WAIT1();    // chunk i's W resident
        } else {
            CP_WAIT0();
        }

        // ---- produce activations for chunk i into sA ----
        {
            const int d_a = i * DPC + 2 * dp;
            const int d_b = d_a + 1;
            const int ca = d_a / 9, ra = d_a - ca * 9;
            const int cb = d_b / 9, rb = d_b - cb * 9;
            const int kha = ra / 3, kwa = ra - kha * 3;
            const int khb = rb / 3, kwb = rb - khb * 3;
#pragma unroll
            for (int it = 0; it < 4; ++it) {
                const int r = rr + it * 32;
                const int ho = ho_b + (r >> 6);
                const int wo = r & 63;
                const int ha = ho + kha - 1, wa = wo + kwa - 1;
                const int hb = ho + khb - 1, wb_ = wo + kwb - 1;
                float va = 0.0f, vb = 0.0f;
                if ((unsigned)ha < HW && (unsigned)wa < HW)
                    va = xb[(ca * HW + ha) * HW + wa];
                if ((unsigned)hb < HW && (unsigned)wb_ < HW)
                    vb = xb[(cb * HW + hb) * HW + wb_];
                float a2[18];
                acts9(va, a2);
                acts9(vb, a2 + 9);
                uint32_t* dst = (uint32_t*)(sA + r * PITCH + dp * 36);
#pragma unroll
                for (int j = 0; j < 9; ++j) {
                    __half2 hh = __floats2half2_rn(a2[2 * j], a2[2 * j + 1]);
                    dst[j] = *(uint32_t*)&hh;
                }
            }
        }
        __syncthreads();   // sA + sW[i&1] ready for all warps

        // ---- MMA: 9 k16 steps ----
        const char* sWp = sW[i & 1];
        const int lr4 = lane >> 2;
        const int lk  = (lane & 3) * 4;   // bytes
#pragma unroll
        for (int ks = 0; ks < 9; ++ks) {
            const int kb = ks * 32;       // bytes (16 halves)
            uint32_t af[4][4];
#pragma unroll
            for (int am = 0; am < 4; ++am) {
                const char* ar = sA + (wm * 64 + am * 16 + lr4) * PITCH + kb + lk;
                af[am][0] = *(const uint32_t*)(ar);
                af[am][1] = *(const uint32_t*)(ar + 8 * PITCH);
                af[am][2] = *(const uint32_t*)(ar + 16);
                af[am][3] = *(const uint32_t*)(ar + 8 * PITCH + 16);
            }
            uint32_t bf[4][2];
#pragma unroll
            for (int bn = 0; bn < 4; ++bn) {
                const char* br = sWp + (wn * 32 + bn * 8 + lr4) * PITCH + kb + lk;
                bf[bn][0] = *(const uint32_t*)(br);
                bf[bn][1] = *(const uint32_t*)(br + 16);
            }
#pragma unroll
            for (int am = 0; am < 4; ++am)
#pragma unroll
                for (int bn = 0; bn < 4; ++bn)
                    mma16816(acc[am][bn], af[am], bf[bn][0], bf[bn][1]);
        }
    }

    __syncthreads();   // done with all tile buffers

    // ---- epilogue: stage C [m][oc] (pitch 130 floats), coalesced writes ----
    float* sepi = (float*)smem;
#pragma unroll
    for (int am = 0; am < 4; ++am)
#pragma unroll
        for (int bn = 0; bn < 4; ++bn) {
            int m = wm * 64 + am * 16 + (lane >> 2);
            int n = wn * 32 + bn * 8 + (lane & 3) * 2;
            *(float2*)&sepi[m * 130 + n]       = make_float2(acc[am][bn][0], acc[am][bn][1]);
            *(float2*)&sepi[(m + 8) * 130 + n] = make_float2(acc[am][bn][2], acc[am][bn][3]);
        }
    __syncthreads();

    float* outb = out + ((size_t)bi * OC << 12);
#pragma unroll
    for (int j = 0; j < (128 * OC) / (GT * 4); ++j) {
        int idx = tid + j * GT;           // float4 units
        int oc = idx >> 5;
        int i0 = (idx & 31) * 4;
        float4 v;
        v.x = sepi[(i0 + 0) * 130 + oc];
        v.y = sepi[(i0 + 1) * 130 + oc];
        v.z = sepi[(i0 + 2) * 130 + oc];
        v.w = sepi[(i0 + 3) * 130 + oc];
        *(float4*)&outb[((size_t)oc << 12) + s_base + i0] = v;
    }
}

// ---------------------------------------------------------------------------
extern "C" void kernel_launch(void* const* d_in, const int* in_sizes, int n_in,
                              void* d_out, int out_size) {
    const float* x  = (const float*)d_in[0];
    const float* bw = (const float*)d_in[1];
    const float* sw = (const float*)d_in[2];
    const float* ss = (const float*)d_in[3];
    float* out = (float*)d_out;

    static const int FUSED_SMEM = 1024 + 3 * TILEB;   // 117760
    cudaFuncSetAttribute(kan_fused_kernel,
                         cudaFuncAttributeMaxDynamicSharedMemorySize, FUSED_SMEM);

    kan_wcomb_kernel<<<(NCH * OC * KHC + 255) / 256, 256>>>(bw, sw, ss);
    kan_fused_kernel<<<NROWS / 128, GT, FUSED_SMEM>>>(x, out);
}

// round 8
// speedup vs baseline: 1.0691x; 1.0691x over previous
#include <cuda_runtime.h>
#include <cuda_fp16.h>
#include <cstdint>

// ============================================================================
// KANConv2d fused, warp-specialized:
//   out[16384,128] = A[16384,5184] @ Wc[5184,128]
// 512 threads/CTA: warps 0-7 = MMA consumers (M=128 x N=128 tile),
//                  warps 8-15 = producers (activations -> sA, cp.async W -> sW).
// Double-buffered sA and sW; named-barrier FULL/EMPTY handshake.
// K chunks of 16 patch-features = 144 halves = 9 m16n8k16 steps.
// ============================================================================

#define OC      128
#define D_TOT   576
#define NBAS    8
#define NCH     36
#define DPC     16
#define KHC     144
#define PITCH   304           // bytes per SMEM tile row (288 + 16 pad)
#define NROWS   16384
#define HW      64
#define TILEB   (128 * PITCH) // 38912

#define BAR_FULL0  1
#define BAR_EMPTY0 3
#define NT 512

__device__ __align__(16) __half g_Wb[(size_t)NCH * OC * KHC];  // 1.33 MB

// ---------------------------------------------------------------------------
__device__ __forceinline__ uint32_t smem_u32(const void* p) {
    uint32_t a;
    asm("{ .reg .u64 t; cvta.to.shared.u64 t, %1; cvt.u32.u64 %0, t; }"
        : "=r"(a) : "l"(p));
    return a;
}
#define CP_ASYNC16(sa, gp) \
    asm volatile("cp.async.cg.shared.global [%0], [%1], 16;" \
        :: "r"((uint32_t)(sa)), "l"(gp) : "memory")
#define CP_COMMIT() asm volatile("cp.async.commit_group;" ::: "memory")
#define CP_WAIT0()  asm volatile("cp.async.wait_group 0;" ::: "memory")
#define BAR_SYNC(id)   asm volatile("bar.sync %0, %1;"   :: "r"(id), "n"(NT) : "memory")
#define BAR_ARRIVE(id) asm volatile("bar.arrive %0, %1;" :: "r"(id), "n"(NT) : "memory")

__device__ __forceinline__ void mma16816(float c[4], const uint32_t a[4],
                                         uint32_t b0, uint32_t b1) {
    asm volatile(
        "mma.sync.aligned.m16n8k16.row.col.f32.f16.f16.f32 "
        "{%0,%1,%2,%3}, {%4,%5,%6,%7}, {%8,%9}, {%0,%1,%2,%3};"
        : "+f"(c[0]), "+f"(c[1]), "+f"(c[2]), "+f"(c[3])
        : "r"(a[0]), "r"(a[1]), "r"(a[2]), "r"(a[3]), "r"(b0), "r"(b1));
}

// ---------------------------------------------------------------------------
// Closed-form activations: silu + 8 uniform cubic B-spline bases.
// ---------------------------------------------------------------------------
__device__ __forceinline__ void acts9(float v, float o[9]) {
    o[0] = v * (1.0f / (1.0f + __expf(-v)));
    float tpos = (v + 2.2f) * 2.5f;
    float fi = floorf(tpos);
    int i = (int)fi;
    float u = tpos - fi;
    bool valid = (i >= 0) && (i <= 10);
    float u2 = u * u, u3 = u2 * u;
    float P0 = u3 * (1.0f / 6.0f);
    float P1 = (((-3.0f * u + 3.0f) * u + 3.0f) * u + 1.0f) * (1.0f / 6.0f);
    float P2 = ((3.0f * u - 6.0f) * u2 + 4.0f) * (1.0f / 6.0f);
    float om = 1.0f - u;
    float P3 = om * om * om * (1.0f / 6.0f);
#pragma unroll
    for (int k = 0; k < 8; ++k) {
        int dlt = i - k;
        float bv = (dlt == 0) ? P0 : (dlt == 1) ? P1 : (dlt == 2) ? P2
                 : (dlt == 3) ? P3 : 0.0f;
        o[1 + k] = valid ? bv : 0.0f;
    }
}

// ---------------------------------------------------------------------------
// Prep kernel: combined weights -> g_Wb[chunk][oc][144] fp16
// ---------------------------------------------------------------------------
__global__ void kan_wcomb_kernel(const float* __restrict__ bw,
                                 const float* __restrict__ sw,
                                 const float* __restrict__ ss) {
    int idx = blockIdx.x * blockDim.x + threadIdx.x;
    if (idx >= NCH * OC * KHC) return;
    int chunk = idx / (OC * KHC);
    int r2    = idx - chunk * (OC * KHC);
    int oc    = r2 / KHC;
    int kl    = r2 - oc * KHC;
    int d     = chunk * DPC + kl / 9;
    int kc    = kl - (kl / 9) * 9;
    float v;
    if (kc == 0) v = bw[oc * D_TOT + d];
    else         v = sw[(oc * D_TOT + d) * NBAS + (kc - 1)] * ss[oc * D_TOT + d];
    g_Wb[idx] = __float2half_rn(v);
}

// ---------------------------------------------------------------------------
// Fused main kernel, warp-specialized.
// SMEM: [sW0][sW1][sA0][sA1], each TILEB.
// ---------------------------------------------------------------------------
__global__ __launch_bounds__(NT, 1)
void kan_fused_kernel(const float* __restrict__ x, float* __restrict__ out) {
    extern __shared__ char dynsmem[];
    const int tid  = threadIdx.x;
    const int lane = tid & 31;
    const int mtile = blockIdx.x;

    uint32_t raw = smem_u32(dynsmem);
    uint32_t base = (raw + 1023) & ~1023u;
    char* smem = dynsmem + (base - raw);
    char* sW[2] = { smem,              smem + TILEB };
    char* sA[2] = { smem + 2 * TILEB,  smem + 3 * TILEB };

    const int bi     = mtile >> 5;
    const int s_base = (mtile * 128) & 4095;
    const int ho_b   = s_base >> 6;
    const float* xb  = x + ((size_t)bi * 64 << 12);

    if (tid < 256) {
        // ===================== CONSUMERS: 8 warps, 2(M) x 4(N) ==============
        const int wid = tid >> 5;
        const int wm  = wid & 1;
        const int wn  = wid >> 1;
        const int lr4 = lane >> 2;
        const int lk  = (lane & 3) * 4;

        float acc[4][4][4];
#pragma unroll
        for (int i = 0; i < 4; ++i)
#pragma unroll
            for (int j = 0; j < 4; ++j)
#pragma unroll
                for (int k = 0; k < 4; ++k) acc[i][j][k] = 0.0f;

        for (int i = 0; i < NCH; ++i) {
            const int b = i & 1;
            BAR_SYNC(BAR_FULL0 + b);
            const char* sAp = sA[b];
            const char* sWp = sW[b];
#pragma unroll
            for (int ks = 0; ks < 9; ++ks) {
                const int kb = ks * 32;
                uint32_t af[4][4];
#pragma unroll
                for (int am = 0; am < 4; ++am) {
                    const char* ar = sAp + (wm * 64 + am * 16 + lr4) * PITCH + kb + lk;
                    af[am][0] = *(const uint32_t*)(ar);
                    af[am][1] = *(const uint32_t*)(ar + 8 * PITCH);
                    af[am][2] = *(const uint32_t*)(ar + 16);
                    af[am][3] = *(const uint32_t*)(ar + 8 * PITCH + 16);
                }
                uint32_t bf[4][2];
#pragma unroll
                for (int bn = 0; bn < 4; ++bn) {
                    const char* br = sWp + (wn * 32 + bn * 8 + lr4) * PITCH + kb + lk;
                    bf[bn][0] = *(const uint32_t*)(br);
                    bf[bn][1] = *(const uint32_t*)(br + 16);
                }
#pragma unroll
                for (int am = 0; am < 4; ++am)
#pragma unroll
                    for (int bn = 0; bn < 4; ++bn)
                        mma16816(acc[am][bn], af[am], bf[bn][0], bf[bn][1]);
            }
            BAR_ARRIVE(BAR_EMPTY0 + b);
        }

        __syncthreads();   // all 512: buffers free for epilogue
        float* sepi = (float*)smem;
#pragma unroll
        for (int am = 0; am < 4; ++am)
#pragma unroll
            for (int bn = 0; bn < 4; ++bn) {
                int m = wm * 64 + am * 16 + (lane >> 2);
                int n = wn * 32 + bn * 8 + (lane & 3) * 2;
                *(float2*)&sepi[m * 130 + n]       = make_float2(acc[am][bn][0], acc[am][bn][1]);
                *(float2*)&sepi[(m + 8) * 130 + n] = make_float2(acc[am][bn][2], acc[am][bn][3]);
            }
    } else {
        // ===================== PRODUCERS: acts + W cp.async =================
        const int tp = tid - 256;
        const int dp = tp & 7;
        const int rr = tp >> 3;
        const int w_oc   = tp >> 1;
        const int w_half = tp & 1;
        const uint32_t w_sm_off = (uint32_t)w_oc * PITCH + w_half * 144;
        const __half* w_gl = g_Wb + (size_t)w_oc * KHC + w_half * 72;

        for (int i = 0; i < NCH; ++i) {
            const int b = i & 1;
            if (i >= 2) BAR_SYNC(BAR_EMPTY0 + b);

            // W chunk i -> sW[b]
            {
                uint32_t dsm = smem_u32(sW[b]) + w_sm_off;
                const __half* gsrc = w_gl + (size_t)i * OC * KHC;
#pragma unroll
                for (int j = 0; j < 9; ++j)
                    CP_ASYNC16(dsm + j * 16, gsrc + j * 8);
                CP_COMMIT();
            }

            // acts chunk i -> sA[b]
            {
                const int d_a = i * DPC + 2 * dp;
                const int d_b = d_a + 1;
                const int ca = d_a / 9, ra = d_a - ca * 9;
                const int cb = d_b / 9, rb = d_b - cb * 9;
                const int kha = ra / 3, kwa = ra - kha * 3;
                const int khb = rb / 3, kwb = rb - khb * 3;
                char* sAp = sA[b];
#pragma unroll
                for (int it = 0; it < 4; ++it) {
                    const int r = rr + it * 32;
                    const int ho = ho_b + (r >> 6);
                    const int wo = r & 63;
                    const int ha = ho + kha - 1, wa = wo + kwa - 1;
                    const int hb = ho + khb - 1, wb_ = wo + kwb - 1;
                    float va = 0.0f, vb = 0.0f;
                    if ((unsigned)ha < HW && (unsigned)wa < HW)
                        va = xb[(ca * HW + ha) * HW + wa];
                    if ((unsigned)hb < HW && (unsigned)wb_ < HW)
                        vb = xb[(cb * HW + hb) * HW + wb_];
                    float a2[18];
                    acts9(va, a2);
                    acts9(vb, a2 + 9);
                    uint32_t* dst = (uint32_t*)(sAp + r * PITCH + dp * 36);
#pragma unroll
                    for (int j = 0; j < 9; ++j) {
                        __half2 hh = __floats2half2_rn(a2[2 * j], a2[2 * j + 1]);
                        dst[j] = *(uint32_t*)&hh;
                    }
                }
            }
            CP_WAIT0();
            BAR_ARRIVE(BAR_FULL0 + b);
        }
        __syncthreads();   // all 512
    }

    __syncthreads();   // sepi staged

    // ---- coalesced global write (all 512 threads) ----
    float* sepi = (float*)smem;
    float* outb = out + ((size_t)bi * OC << 12);
#pragma unroll
    for (int j = 0; j < (128 * OC) / (NT * 4); ++j) {
        int idx = tid + j * NT;           // float4 units
        int oc = idx >> 5;
        int i0 = (idx & 31) * 4;
        float4 v;
        v.x = sepi[(i0 + 0) * 130 + oc];
        v.y = sepi[(i0 + 1) * 130 + oc];
        v.z = sepi[(i0 + 2) * 130 + oc];
        v.w = sepi[(i0 + 3) * 130 + oc];
        *(float4*)&outb[((size_t)oc << 12) + s_base + i0] = v;
    }
}

// ---------------------------------------------------------------------------
extern "C" void kernel_launch(void* const* d_in, const int* in_sizes, int n_in,
                              void* d_out, int out_size) {
    const float* x  = (const float*)d_in[0];
    const float* bw = (const float*)d_in[1];
    const float* sw = (const float*)d_in[2];
    const float* ss = (const float*)d_in[3];
    float* out = (float*)d_out;

    static const int FUSED_SMEM = 1024 + 4 * TILEB;   // 156672
    cudaFuncSetAttribute(kan_fused_kernel,
                         cudaFuncAttributeMaxDynamicSharedMemorySize, FUSED_SMEM);

    kan_wcomb_kernel<<<(NCH * OC * KHC + 255) / 256, 256>>>(bw, sw, ss);
    kan_fused_kernel<<<NROWS / 128, NT, FUSED_SMEM>>>(x, out);
}

// round 16
// speedup vs baseline: 1.4540x; 1.3601x over previous
#include <cuda_runtime.h>
#include <cuda_fp16.h>
#include <cstdint>

// ============================================================================
// KANConv2d, 3-kernel pipeline v2 (fixed staging pitch):
//   out[16384,128] = A[16384,5184] @ Wc[5184,128]
//   (1) act kernel: closed-form silu+cubic-B-spline -> g_A fp16 [n][5184]
//       warp-per-d mapping (coalesced x loads), SMEM-staged coalesced writes
//   (2) wcomb: combined weights -> g_Wb fp16 [oc][5184]
//   (3) GEMM: mma.sync m16n8k16, M-tile 64, grid 256, cp.async + SW128 + ldsm
// ============================================================================

#define OC      128
#define D_TOT   576
#define NBAS    8
#define NK      5184
#define KC      64            // halves per GEMM chunk (128 B)
#define NCHUNK  81
#define NROWS   16384
#define HW      64

__device__ __align__(16) __half g_A[(size_t)NROWS * NK];   // ~170 MB scratch
__device__ __align__(16) __half g_Wb[(size_t)OC * NK];     // 1.33 MB

// ---------------------------------------------------------------------------
__device__ __forceinline__ uint32_t smem_u32(const void* p) {
    uint32_t a;
    asm("{ .reg .u64 t; cvta.to.shared.u64 t, %1; cvt.u32.u64 %0, t; }"
        : "=r"(a) : "l"(p));
    return a;
}
#define CP_ASYNC16(sa, gp) \
    asm volatile("cp.async.cg.shared.global [%0], [%1], 16;" \
        :: "r"((uint32_t)(sa)), "l"(gp) : "memory")
#define CP_COMMIT() asm volatile("cp.async.commit_group;" ::: "memory")
#define CP_WAIT0()  asm volatile("cp.async.wait_group 0;" ::: "memory")
#define SW128(off) ((off) ^ (((off) >> 3) & 0x70))

__device__ __forceinline__ void ldsm_x4(uint32_t r[4], uint32_t addr) {
    asm volatile("ldmatrix.sync.aligned.m8n8.x4.shared.b16 {%0,%1,%2,%3}, [%4];"
                 : "=r"(r[0]), "=r"(r[1]), "=r"(r[2]), "=r"(r[3]) : "r"(addr));
}
__device__ __forceinline__ void mma16816(float c[4], const uint32_t a[4],
                                         uint32_t b0, uint32_t b1) {
    asm volatile(
        "mma.sync.aligned.m16n8k16.row.col.f32.f16.f16.f32 "
        "{%0,%1,%2,%3}, {%4,%5,%6,%7}, {%8,%9}, {%0,%1,%2,%3};"
        : "+f"(c[0]), "+f"(c[1]), "+f"(c[2]), "+f"(c[3])
        : "r"(a[0]), "r"(a[1]), "r"(a[2]), "r"(a[3]), "r"(b0), "r"(b1));
}

// ---------------------------------------------------------------------------
// Closed-form activations: silu + 8 uniform cubic B-spline bases.
// ---------------------------------------------------------------------------
__device__ __forceinline__ void acts9(float v, float o[9]) {
    o[0] = v * (1.0f / (1.0f + __expf(-v)));
    float tpos = (v + 2.2f) * 2.5f;
    float fi = floorf(tpos);
    int i = (int)fi;
    float u = tpos - fi;
    bool valid = (i >= 0) && (i <= 10);
    float u2 = u * u, u3 = u2 * u;
    float P0 = u3 * (1.0f / 6.0f);
    float P1 = (((-3.0f * u + 3.0f) * u + 3.0f) * u + 1.0f) * (1.0f / 6.0f);
    float P2 = ((3.0f * u - 6.0f) * u2 + 4.0f) * (1.0f / 6.0f);
    float om = 1.0f - u;
    float P3 = om * om * om * (1.0f / 6.0f);
#pragma unroll
    for (int k = 0; k < 8; ++k) {
        int dlt = i - k;
        float bv = (dlt == 0) ? P0 : (dlt == 1) ? P1 : (dlt == 2) ? P2
                 : (dlt == 3) ? P3 : 0.0f;
        o[1 + k] = valid ? bv : 0.0f;
    }
}

// ---------------------------------------------------------------------------
// Kernel 1: activations. CTA = 64 rows, 256 thr.
// 18 groups of 32 d; each warp handles 4 d x 64 rows (lanes = consecutive px).
// Staged row = 32 d x 9 halves = 576 B; pitch 584 B.
// ---------------------------------------------------------------------------
#define AP 584
__global__ __launch_bounds__(256)
void kan_act_kernel(const float* __restrict__ x) {
    __shared__ char sT[64 * AP];   // 37376 B
    const int tid  = threadIdx.x;
    const int lane = tid & 31;
    const int wrp  = tid >> 5;
    const int n0   = blockIdx.x * 64;
    const int bi   = n0 >> 12;
    const int sb   = n0 & 4095;
    const int ho   = sb >> 6;          // all 64 rows share ho
    const float* xb = x + ((size_t)bi * 64 << 12);

    for (int g = 0; g < 18; ++g) {
        const int d0 = g * 32;
#pragma unroll
        for (int dd = 0; dd < 4; ++dd) {
            const int dl = wrp * 4 + dd;       // 0..31
            const int d  = d0 + dl;
            const int c  = d / 9;
            const int r9 = d - c * 9;
            const int kh = r9 / 3, kw = r9 - kh * 3;
            const int h  = ho + kh - 1;
            const bool hv = (unsigned)h < (unsigned)HW;
            const float* xrow = xb + (c * HW + h) * HW;
#pragma unroll
            for (int it = 0; it < 2; ++it) {
                const int r  = lane + it * 32;
                const int w_ = r + kw - 1;
                float v = 0.0f;
                if (hv && (unsigned)w_ < (unsigned)HW) v = xrow[w_];
                float a9[9];
                acts9(v, a9);
                __half* dst = (__half*)(sT + r * AP + dl * 18);
#pragma unroll
                for (int j = 0; j < 9; ++j) dst[j] = __float2half_rn(a9[j]);
            }
        }
        __syncthreads();
        // writeout: 64 rows x 144 words, coalesced
        uint32_t* gA32 = (uint32_t*)g_A;
#pragma unroll
        for (int jj = 0; jj < 36; ++jj) {
            int idx = tid + jj * 256;
            int row = idx / 144;
            int col = idx - row * 144;
            gA32[(size_t)(n0 + row) * (NK / 2) + g * 144 + col] =
                *(const uint32_t*)(sT + row * AP + col * 4);
        }
        __syncthreads();
    }
}

// ---------------------------------------------------------------------------
// Kernel 2: combined weights -> g_Wb[oc][5184]
// ---------------------------------------------------------------------------
__global__ void kan_wcomb_kernel(const float* __restrict__ bw,
                                 const float* __restrict__ sw,
                                 const float* __restrict__ ss) {
    int idx = blockIdx.x * blockDim.x + threadIdx.x;
    if (idx >= OC * NK) return;
    int oc  = idx / NK;
    int rem = idx - oc * NK;
    int d   = rem / 9;
    int kc  = rem - d * 9;
    float v;
    if (kc == 0) v = bw[oc * D_TOT + d];
    else         v = sw[(oc * D_TOT + d) * NBAS + (kc - 1)] * ss[oc * D_TOT + d];
    g_Wb[idx] = __float2half_rn(v);
}

// ---------------------------------------------------------------------------
// Kernel 3: HMMA GEMM. grid = 256 M-tiles of 64; CTA: M=64, N=128.
// 8 warps: 2(M) x 4(N), warp tile 32x32 = 2x4 m16n8k16 frags.
// Double-buffered SW128 tiles via cp.async.
// ---------------------------------------------------------------------------
#define GT 256
#define A_TILEB  (64 * 128)    // 8192
#define W_TILEB  (128 * 128)   // 16384

__global__ __launch_bounds__(GT)
void kan_gemm_kernel(float* __restrict__ out) {
    extern __shared__ char dynsmem[];
    const int tid  = threadIdx.x;
    const int lane = tid & 31;
    const int wid  = tid >> 5;
    const int wm   = wid & 1;     // M 0/32
    const int wn   = wid >> 1;    // N 0/32/64/96
    const int mtile = blockIdx.x;

    uint32_t raw = smem_u32(dynsmem);
    uint32_t smadr = (raw + 1023) & ~1023u;
    char* smem = dynsmem + (smadr - raw);

    const uint32_t aBuf[2] = { smadr,             smadr + A_TILEB };
    const uint32_t wBuf[2] = { smadr + 2*A_TILEB, smadr + 2*A_TILEB + W_TILEB };

    const __half* Abase = g_A + (size_t)mtile * 64 * NK;
    const __half* Wbase = g_Wb;

    int a_goff[2], a_soff[2];
#pragma unroll
    for (int it = 0; it < 2; ++it) {
        int idx = tid + it * GT;          // 0..511
        int row = idx >> 3, cc = idx & 7;
        a_goff[it] = row * NK + cc * 8;
        a_soff[it] = SW128(row * 128 + cc * 16);
    }
    int w_goff[4], w_soff[4];
#pragma unroll
    for (int it = 0; it < 4; ++it) {
        int idx = tid + it * GT;          // 0..1023
        int row = idx >> 3, cc = idx & 7;
        w_goff[it] = row * NK + cc * 8;
        w_soff[it] = SW128(row * 128 + cc * 16);
    }

    float acc[2][4][4];
#pragma unroll
    for (int i = 0; i < 2; ++i)
#pragma unroll
        for (int j = 0; j < 4; ++j)
#pragma unroll
            for (int k = 0; k < 4; ++k) acc[i][j][k] = 0.0f;

    const int lr  = lane & 15;
    const int lcb = (lane >> 4) * 16;

    // prefetch chunk 0
#pragma unroll
    for (int it = 0; it < 2; ++it) CP_ASYNC16(aBuf[0] + a_soff[it], Abase + a_goff[it]);
#pragma unroll
    for (int it = 0; it < 4; ++it) CP_ASYNC16(wBuf[0] + w_soff[it], Wbase + w_goff[it]);
    CP_COMMIT();

    for (int i = 0; i < NCHUNK; ++i) {
        CP_WAIT0();
        __syncthreads();
        if (i + 1 < NCHUNK) {
            const int b2 = (i + 1) & 1;
            const int k0 = (i + 1) * KC;
#pragma unroll
            for (int it = 0; it < 2; ++it)
                CP_ASYNC16(aBuf[b2] + a_soff[it], Abase + a_goff[it] + k0);
#pragma unroll
            for (int it = 0; it < 4; ++it)
                CP_ASYNC16(wBuf[b2] + w_soff[it], Wbase + w_goff[it] + k0);
            CP_COMMIT();
        }
        const int b = i & 1;
        const uint32_t aB = aBuf[b], wB = wBuf[b];
#pragma unroll
        for (int ks = 0; ks < 4; ++ks) {
            const int colb = ks * 32 + lcb;
            uint32_t af[2][4];
#pragma unroll
            for (int am = 0; am < 2; ++am) {
                int row = wm * 32 + am * 16 + lr;
                ldsm_x4(af[am], aB + SW128(row * 128 + colb));
            }
            uint32_t bf[2][4];
#pragma unroll
            for (int bp = 0; bp < 2; ++bp) {
                int row = wn * 32 + bp * 16 + lr;
                ldsm_x4(bf[bp], wB + SW128(row * 128 + colb));
            }
#pragma unroll
            for (int am = 0; am < 2; ++am)
#pragma unroll
                for (int bn = 0; bn < 4; ++bn) {
                    const int bp = bn >> 1, j = bn & 1;
                    mma16816(acc[am][bn], af[am], bf[bp][j], bf[bp][j + 2]);
                }
        }
    }

    __syncthreads();

    // epilogue: stage C [64][130] fp32, then coalesced writes
    float* sepi = (float*)smem;
#pragma unroll
    for (int am = 0; am < 2; ++am)
#pragma unroll
        for (int bn = 0; bn < 4; ++bn) {
            int m = wm * 32 + am * 16 + (lane >> 2);
            int n = wn * 32 + bn * 8 + (lane & 3) * 2;
            *(float2*)&sepi[m * 130 + n]       = make_float2(acc[am][bn][0], acc[am][bn][1]);
            *(float2*)&sepi[(m + 8) * 130 + n] = make_float2(acc[am][bn][2], acc[am][bn][3]);
        }
    __syncthreads();

    const int bi     = mtile >> 6;
    const int s_base = (mtile * 64) & 4095;
    float* outb = out + ((size_t)bi * OC << 12);
#pragma unroll
    for (int j = 0; j < (64 * OC) / (GT * 4); ++j) {
        int idx = tid + j * GT;            // float4 units
        int oc = idx >> 4;
        int i0 = (idx & 15) * 4;
        float4 v;
        v.x = sepi[(i0 + 0) * 130 + oc];
        v.y = sepi[(i0 + 1) * 130 + oc];
        v.z = sepi[(i0 + 2) * 130 + oc];
        v.w = sepi[(i0 + 3) * 130 + oc];
        *(float4*)&outb[((size_t)oc << 12) + s_base + i0] = v;
    }
}

// ---------------------------------------------------------------------------
extern "C" void kernel_launch(void* const* d_in, const int* in_sizes, int n_in,
                              void* d_out, int out_size) {
    const float* x  = (const float*)d_in[0];
    const float* bw = (const float*)d_in[1];
    const float* sw = (const float*)d_in[2];
    const float* ss = (const float*)d_in[3];
    float* out = (float*)d_out;

    static const int GEMM_SMEM = 1024 + 2 * A_TILEB + 2 * W_TILEB;  // 50176
    cudaFuncSetAttribute(kan_gemm_kernel,
                         cudaFuncAttributeMaxDynamicSharedMemorySize, GEMM_SMEM);

    kan_wcomb_kernel<<<(OC * NK + 255) / 256, 256>>>(bw, sw, ss);
    kan_act_kernel<<<NROWS / 64, 256>>>(x);
    kan_gemm_kernel<<<NROWS / 64, GT, GEMM_SMEM>>>(out);
}

// round 17
// speedup vs baseline: 1.4558x; 1.0012x over previous
#include <cuda_runtime.h>
#include <cuda_fp16.h>
#include <cstdint>

// ============================================================================
// KANConv2d, 3-kernel pipeline v3:
//   out[16384,128] = A[16384,5184] @ Wc[5184,128]
//   (1) act: closed-form silu+cubic-B-spline -> g_A fp16 [n][5184]
//   (2) wcomb: combined weights -> g_Wb fp16 [oc][5184]
//   (3) GEMM: mma.sync m16n8k16, M-tile 64, grid 256,
//       4-deep cp.async ring (prefetch distance 3) + SW128 + ldmatrix
// ============================================================================

#define OC      128
#define D_TOT   576
#define NBAS    8
#define NK      5184
#define KC      64            // halves per GEMM chunk (128 B)
#define NCHUNK  81
#define NROWS   16384
#define HW      64

__device__ __align__(16) __half g_A[(size_t)NROWS * NK];   // ~170 MB scratch
__device__ __align__(16) __half g_Wb[(size_t)OC * NK];     // 1.33 MB

// ---------------------------------------------------------------------------
__device__ __forceinline__ uint32_t smem_u32(const void* p) {
    uint32_t a;
    asm("{ .reg .u64 t; cvta.to.shared.u64 t, %1; cvt.u32.u64 %0, t; }"
        : "=r"(a) : "l"(p));
    return a;
}
#define CP_ASYNC16(sa, gp) \
    asm volatile("cp.async.cg.shared.global [%0], [%1], 16;" \
        :: "r"((uint32_t)(sa)), "l"(gp) : "memory")
#define CP_COMMIT() asm volatile("cp.async.commit_group;" ::: "memory")
#define CP_WAITN(n) asm volatile("cp.async.wait_group %0;" :: "n"(n) : "memory")
#define SW128(off) ((off) ^ (((off) >> 3) & 0x70))

__device__ __forceinline__ void ldsm_x4(uint32_t r[4], uint32_t addr) {
    asm volatile("ldmatrix.sync.aligned.m8n8.x4.shared.b16 {%0,%1,%2,%3}, [%4];"
                 : "=r"(r[0]), "=r"(r[1]), "=r"(r[2]), "=r"(r[3]) : "r"(addr));
}
__device__ __forceinline__ void mma16816(float c[4], const uint32_t a[4],
                                         uint32_t b0, uint32_t b1) {
    asm volatile(
        "mma.sync.aligned.m16n8k16.row.col.f32.f16.f16.f32 "
        "{%0,%1,%2,%3}, {%4,%5,%6,%7}, {%8,%9}, {%0,%1,%2,%3};"
        : "+f"(c[0]), "+f"(c[1]), "+f"(c[2]), "+f"(c[3])
        : "r"(a[0]), "r"(a[1]), "r"(a[2]), "r"(a[3]), "r"(b0), "r"(b1));
}

// ---------------------------------------------------------------------------
// Closed-form activations: silu + 8 uniform cubic B-spline bases.
// ---------------------------------------------------------------------------
__device__ __forceinline__ void acts9(float v, float o[9]) {
    o[0] = v * (1.0f / (1.0f + __expf(-v)));
    float tpos = (v + 2.2f) * 2.5f;
    float fi = floorf(tpos);
    int i = (int)fi;
    float u = tpos - fi;
    bool valid = (i >= 0) && (i <= 10);
    float u2 = u * u, u3 = u2 * u;
    float P0 = u3 * (1.0f / 6.0f);
    float P1 = (((-3.0f * u + 3.0f) * u + 3.0f) * u + 1.0f) * (1.0f / 6.0f);
    float P2 = ((3.0f * u - 6.0f) * u2 + 4.0f) * (1.0f / 6.0f);
    float om = 1.0f - u;
    float P3 = om * om * om * (1.0f / 6.0f);
#pragma unroll
    for (int k = 0; k < 8; ++k) {
        int dlt = i - k;
        float bv = (dlt == 0) ? P0 : (dlt == 1) ? P1 : (dlt == 2) ? P2
                 : (dlt == 3) ? P3 : 0.0f;
        o[1 + k] = valid ? bv : 0.0f;
    }
}

// ---------------------------------------------------------------------------
// Kernel 1: activations. CTA = 64 rows, 256 thr. (unchanged from R16 pass)
// ---------------------------------------------------------------------------
#define AP 584
__global__ __launch_bounds__(256)
void kan_act_kernel(const float* __restrict__ x) {
    __shared__ char sT[64 * AP];
    const int tid  = threadIdx.x;
    const int lane = tid & 31;
    const int wrp  = tid >> 5;
    const int n0   = blockIdx.x * 64;
    const int bi   = n0 >> 12;
    const int sb   = n0 & 4095;
    const int ho   = sb >> 6;
    const float* xb = x + ((size_t)bi * 64 << 12);

    for (int g = 0; g < 18; ++g) {
        const int d0 = g * 32;
#pragma unroll
        for (int dd = 0; dd < 4; ++dd) {
            const int dl = wrp * 4 + dd;
            const int d  = d0 + dl;
            const int c  = d / 9;
            const int r9 = d - c * 9;
            const int kh = r9 / 3, kw = r9 - kh * 3;
            const int h  = ho + kh - 1;
            const bool hv = (unsigned)h < (unsigned)HW;
            const float* xrow = xb + (c * HW + h) * HW;
#pragma unroll
            for (int it = 0; it < 2; ++it) {
                const int r  = lane + it * 32;
                const int w_ = r + kw - 1;
                float v = 0.0f;
                if (hv && (unsigned)w_ < (unsigned)HW) v = xrow[w_];
                float a9[9];
                acts9(v, a9);
                __half* dst = (__half*)(sT + r * AP + dl * 18);
#pragma unroll
                for (int j = 0; j < 9; ++j) dst[j] = __float2half_rn(a9[j]);
            }
        }
        __syncthreads();
        uint32_t* gA32 = (uint32_t*)g_A;
#pragma unroll
        for (int jj = 0; jj < 36; ++jj) {
            int idx = tid + jj * 256;
            int row = idx / 144;
            int col = idx - row * 144;
            gA32[(size_t)(n0 + row) * (NK / 2) + g * 144 + col] =
                *(const uint32_t*)(sT + row * AP + col * 4);
        }
        __syncthreads();
    }
}

// ---------------------------------------------------------------------------
// Kernel 2: combined weights -> g_Wb[oc][5184]
// ---------------------------------------------------------------------------
__global__ void kan_wcomb_kernel(const float* __restrict__ bw,
                                 const float* __restrict__ sw,
                                 const float* __restrict__ ss) {
    int idx = blockIdx.x * blockDim.x + threadIdx.x;
    if (idx >= OC * NK) return;
    int oc  = idx / NK;
    int rem = idx - oc * NK;
    int d   = rem / 9;
    int kc  = rem - d * 9;
    float v;
    if (kc == 0) v = bw[oc * D_TOT + d];
    else         v = sw[(oc * D_TOT + d) * NBAS + (kc - 1)] * ss[oc * D_TOT + d];
    g_Wb[idx] = __float2half_rn(v);
}

// ---------------------------------------------------------------------------
// Kernel 3: HMMA GEMM, 4-deep cp.async ring (prefetch distance 3).
// grid = 256 M-tiles of 64; CTA: M=64, N=128; 8 warps 2(M) x 4(N).
// ---------------------------------------------------------------------------
#define GT 256
#define A_TILEB  (64 * 128)    // 8192
#define W_TILEB  (128 * 128)   // 16384
#define STAGEB   (A_TILEB + W_TILEB)  // 24576 per stage
#define NSTAGE   4

__global__ __launch_bounds__(GT)
void kan_gemm_kernel(float* __restrict__ out) {
    extern __shared__ char dynsmem[];
    const int tid  = threadIdx.x;
    const int lane = tid & 31;
    const int wid  = tid >> 5;
    const int wm   = wid & 1;
    const int wn   = wid >> 1;
    const int mtile = blockIdx.x;

    uint32_t raw = smem_u32(dynsmem);
    uint32_t smadr = (raw + 1023) & ~1023u;
    char* smem = dynsmem + (smadr - raw);

    uint32_t aBuf[NSTAGE], wBuf[NSTAGE];
#pragma unroll
    for (int s = 0; s < NSTAGE; ++s) {
        aBuf[s] = smadr + s * STAGEB;
        wBuf[s] = smadr + s * STAGEB + A_TILEB;
    }

    const __half* Abase = g_A + (size_t)mtile * 64 * NK;
    const __half* Wbase = g_Wb;

    int a_goff[2], a_soff[2];
#pragma unroll
    for (int it = 0; it < 2; ++it) {
        int idx = tid + it * GT;
        int row = idx >> 3, cc = idx & 7;
        a_goff[it] = row * NK + cc * 8;
        a_soff[it] = SW128(row * 128 + cc * 16);
    }
    int w_goff[4], w_soff[4];
#pragma unroll
    for (int it = 0; it < 4; ++it) {
        int idx = tid + it * GT;
        int row = idx >> 3, cc = idx & 7;
        w_goff[it] = row * NK + cc * 8;
        w_soff[it] = SW128(row * 128 + cc * 16);
    }

    float acc[2][4][4];
#pragma unroll
    for (int i = 0; i < 2; ++i)
#pragma unroll
        for (int j = 0; j < 4; ++j)
#pragma unroll
            for (int k = 0; k < 4; ++k) acc[i][j][k] = 0.0f;

    const int lr  = lane & 15;
    const int lcb = (lane >> 4) * 16;

    // prologue: prefetch chunks 0,1,2
#pragma unroll
    for (int p = 0; p < 3; ++p) {
        const int k0 = p * KC;
#pragma unroll
        for (int it = 0; it < 2; ++it)
            CP_ASYNC16(aBuf[p] + a_soff[it], Abase + a_goff[it] + k0);
#pragma unroll
        for (int it = 0; it < 4; ++it)
            CP_ASYNC16(wBuf[p] + w_soff[it], Wbase + w_goff[it] + k0);
        CP_COMMIT();
    }

    for (int i = 0; i < NCHUNK; ++i) {
        // wait so that chunk i is resident
        if (i < NCHUNK - 2)      CP_WAITN(2);
        else if (i == NCHUNK - 2) CP_WAITN(1);
        else                      CP_WAITN(0);
        __syncthreads();   // all warps done with buffer (i+3)&3's previous life

        if (i + 3 < NCHUNK) {
            const int s  = (i + 3) & 3;
            const int k0 = (i + 3) * KC;
#pragma unroll
            for (int it = 0; it < 2; ++it)
                CP_ASYNC16(aBuf[s] + a_soff[it], Abase + a_goff[it] + k0);
#pragma unroll
            for (int it = 0; it < 4; ++it)
                CP_ASYNC16(wBuf[s] + w_soff[it], Wbase + w_goff[it] + k0);
            CP_COMMIT();
        }

        const int b = i & 3;
        const uint32_t aB = aBuf[b], wB = wBuf[b];
#pragma unroll
        for (int ks = 0; ks < 4; ++ks) {
            const int colb = ks * 32 + lcb;
            uint32_t af[2][4];
#pragma unroll
            for (int am = 0; am < 2; ++am) {
                int row = wm * 32 + am * 16 + lr;
                ldsm_x4(af[am], aB + SW128(row * 128 + colb));
            }
            uint32_t bf[2][4];
#pragma unroll
            for (int bp = 0; bp < 2; ++bp) {
                int row = wn * 32 + bp * 16 + lr;
                ldsm_x4(bf[bp], wB + SW128(row * 128 + colb));
            }
#pragma unroll
            for (int am = 0; am < 2; ++am)
#pragma unroll
                for (int bn = 0; bn < 4; ++bn) {
                    const int bp = bn >> 1, j = bn & 1;
                    mma16816(acc[am][bn], af[am], bf[bp][j], bf[bp][j + 2]);
                }
        }
    }

    __syncthreads();

    // epilogue: stage C [64][130] fp32, then coalesced writes
    float* sepi = (float*)smem;
#pragma unroll
    for (int am = 0; am < 2; ++am)
#pragma unroll
        for (int bn = 0; bn < 4; ++bn) {
            int m = wm * 32 + am * 16 + (lane >> 2);
            int n = wn * 32 + bn * 8 + (lane & 3) * 2;
            *(float2*)&sepi[m * 130 + n]       = make_float2(acc[am][bn][0], acc[am][bn][1]);
            *(float2*)&sepi[(m + 8) * 130 + n] = make_float2(acc[am][bn][2], acc[am][bn][3]);
        }
    __syncthreads();

    const int bi     = mtile >> 6;
    const int s_base = (mtile * 64) & 4095;
    float* outb = out + ((size_t)bi * OC << 12);
#pragma unroll
    for (int j = 0; j < (64 * OC) / (GT * 4); ++j) {
        int idx = tid + j * GT;
        int oc = idx >> 4;
        int i0 = (idx & 15) * 4;
        float4 v;
        v.x = sepi[(i0 + 0) * 130 + oc];
        v.y = sepi[(i0 + 1) * 130 + oc];
        v.z = sepi[(i0 + 2) * 130 + oc];
        v.w = sepi[(i0 + 3) * 130 + oc];
        *(float4*)&outb[((size_t)oc << 12) + s_base + i0] = v;
    }
}

// ---------------------------------------------------------------------------
extern "C" void kernel_launch(void* const* d_in, const int* in_sizes, int n_in,
                              void* d_out, int out_size) {
    const float* x  = (const float*)d_in[0];
    const float* bw = (const float*)d_in[1];
    const float* sw = (const float*)d_in[2];
    const float* ss = (const float*)d_in[3];
    float* out = (float*)d_out;

    static const int GEMM_SMEM = 1024 + NSTAGE * STAGEB;   // 99328
    cudaFuncSetAttribute(kan_gemm_kernel,
                         cudaFuncAttributeMaxDynamicSharedMemorySize, GEMM_SMEM);

    // order: act, wcomb, gemm  (ncu -s 5 -c 1 now lands on the GEMM)
    kan_act_kernel<<<NROWS / 64, 256>>>(x);
    kan_wcomb_kernel<<<(OC * NK + 255) / 256, 256>>>(bw, sw, ss);
    kan_gemm_kernel<<<NROWS / 64, GT, GEMM_SMEM>>>(out);
}